// round 1
// baseline (speedup 1.0000x reference)
#include <cuda_runtime.h>

#define Dh 128
#define NHEAD 16
#define NB 2
#define SEQ 2048
#define NHD (NHEAD*Dh)     // 2048
#define MROWS (NB*SEQ)     // 4096

// Scratch (no allocations allowed): Q,K,V and ctx in (B,H,S,D) layout.
__device__ float g_QKV[3][(size_t)NB*NHEAD*SEQ*Dh];
__device__ float g_CTX[(size_t)NB*NHEAD*SEQ*Dh];

// ---------------------------------------------------------------------------
// QKV projection: Y[b,h,s,d] = sum_k X[b,s,k] * W[h*Dh+d, k] + bias[h*Dh+d]
// X: (B*S, 128) row-major; W: (2048, 128) row-major (torch Linear weight).
// 64x64 output tile per block, full K=128 in smem, 256 threads, 4x4 per thread.
// ---------------------------------------------------------------------------
__global__ __launch_bounds__(256) void qkv_gemm_kernel(
    const float* __restrict__ X, const float* __restrict__ W,
    const float* __restrict__ bias, int which)
{
    extern __shared__ float sm[];
    float* Xs = sm;             // 64 x 129
    float* Ws = sm + 64*129;    // 64 x 129

    const int m0 = blockIdx.y * 64;
    const int n0 = blockIdx.x * 64;
    const int tid = threadIdx.x;

    for (int i = tid; i < 64*32; i += 256) {
        int r = i >> 5, c = (i & 31) << 2;
        float4 v = *(const float4*)(X + (size_t)(m0 + r)*Dh + c);
        Xs[r*129 + c]   = v.x; Xs[r*129 + c+1] = v.y;
        Xs[r*129 + c+2] = v.z; Xs[r*129 + c+3] = v.w;
        float4 w = *(const float4*)(W + (size_t)(n0 + r)*Dh + c);
        Ws[r*129 + c]   = w.x; Ws[r*129 + c+1] = w.y;
        Ws[r*129 + c+2] = w.z; Ws[r*129 + c+3] = w.w;
    }
    __syncthreads();

    const int tx = tid & 15, ty = tid >> 4;
    float acc[4][4] = {};
    #pragma unroll 4
    for (int k = 0; k < Dh; ++k) {
        float a[4];
        #pragma unroll
        for (int i = 0; i < 4; ++i) a[i] = Xs[(ty*4 + i)*129 + k];
        #pragma unroll
        for (int j = 0; j < 4; ++j) {
            float bv = Ws[(tx + 16*j)*129 + k];
            #pragma unroll
            for (int i = 0; i < 4; ++i) acc[i][j] += a[i] * bv;
        }
    }

    float* Y = g_QKV[which];
    #pragma unroll
    for (int i = 0; i < 4; ++i) {
        int m = m0 + ty*4 + i;
        int b = m >> 11, s = m & 2047;
        #pragma unroll
        for (int j = 0; j < 4; ++j) {
            int n = n0 + tx + 16*j;
            int h = n >> 7, d = n & 127;
            Y[(((size_t)(b*NHEAD + h))*SEQ + s)*Dh + d] = acc[i][j] + bias[n];
        }
    }
}

// ---------------------------------------------------------------------------
// Fused attention per (b, h, 64 q-rows):
//  phase 1: scores = QK^T*scale + mask*(-1e9); write raw scores into the
//           weights output region; track per-row online (max, sumexp).
//  reduce:  combine partial (m,l) across the 16 tx lanes per row.
//  phase 2: re-read raw scores (L2-resident), w = exp(s-m)/l, write final
//           weights back, accumulate ctx += w @ V.
// ---------------------------------------------------------------------------
__global__ __launch_bounds__(256) void attn_kernel(
    const int* __restrict__ mask, float* __restrict__ weights)
{
    extern __shared__ float sm[];
    float* Qs   = sm;                  // 64*129  (Q tile, K-major stride 129)
    float* Ts   = Qs + 64*129;         // 64*132  (K tile: stride 129 / V tile: stride 132)
    float* wS   = Ts + 64*132;         // 64*65   (softmax weights tile)
    float* redm = wS + 64*65;          // 64*17
    float* redl = redm + 64*17;        // 64*17
    float* mrow = redl + 64*17;        // 64
    float* linv = mrow + 64;           // 64

    const int s0 = blockIdx.x * 64;
    const int h  = blockIdx.y;
    const int b  = blockIdx.z;
    const int tid = threadIdx.x;
    const int tx = tid & 15, ty = tid >> 4;

    const size_t bh = (size_t)(b*NHEAD + h);
    const float* Qg = g_QKV[0] + bh*SEQ*Dh;
    const float* Kg = g_QKV[1] + bh*SEQ*Dh;
    const float* Vg = g_QKV[2] + bh*SEQ*Dh;
    const int*   mb = mask + (size_t)b*SEQ*SEQ;
    float*       wb = weights + bh*SEQ*SEQ;

    // Load Q tile (64 x 128)
    for (int i = tid; i < 64*32; i += 256) {
        int r = i >> 5, c = (i & 31) << 2;
        float4 v = *(const float4*)(Qg + (size_t)(s0 + r)*Dh + c);
        Qs[r*129 + c]   = v.x; Qs[r*129 + c+1] = v.y;
        Qs[r*129 + c+2] = v.z; Qs[r*129 + c+3] = v.w;
    }

    float mloc[4], lloc[4];
    #pragma unroll
    for (int i = 0; i < 4; ++i) { mloc[i] = -1e30f; lloc[i] = 0.f; }
    const float scale = 0.08838834764831845f;   // 1/sqrt(128)

    // ---------------- phase 1 ----------------
    for (int t0 = 0; t0 < SEQ; t0 += 64) {
        __syncthreads();
        for (int i = tid; i < 64*32; i += 256) {
            int r = i >> 5, c = (i & 31) << 2;
            float4 v = *(const float4*)(Kg + (size_t)(t0 + r)*Dh + c);
            Ts[r*129 + c]   = v.x; Ts[r*129 + c+1] = v.y;
            Ts[r*129 + c+2] = v.z; Ts[r*129 + c+3] = v.w;
        }
        __syncthreads();

        float acc[4][4] = {};
        #pragma unroll 4
        for (int k = 0; k < Dh; ++k) {
            float a[4];
            #pragma unroll
            for (int i = 0; i < 4; ++i) a[i] = Qs[(ty*4 + i)*129 + k];
            #pragma unroll
            for (int j = 0; j < 4; ++j) {
                float bv = Ts[(tx + 16*j)*129 + k];
                #pragma unroll
                for (int i = 0; i < 4; ++i) acc[i][j] += a[i] * bv;
            }
        }

        #pragma unroll
        for (int i = 0; i < 4; ++i) {
            int rg = s0 + ty*4 + i;
            float nm = mloc[i];
            #pragma unroll
            for (int j = 0; j < 4; ++j) {
                int t = t0 + tx + 16*j;
                float sc = acc[i][j]*scale + (float)mb[(size_t)rg*SEQ + t] * (-1e9f);
                acc[i][j] = sc;
                wb[(size_t)rg*SEQ + t] = sc;       // raw score (rescaled in phase 2)
                nm = fmaxf(nm, sc);
            }
            if (nm > mloc[i]) { lloc[i] *= __expf(mloc[i] - nm); mloc[i] = nm; }
            #pragma unroll
            for (int j = 0; j < 4; ++j) lloc[i] += __expf(acc[i][j] - nm);
        }
    }

    // ---------------- reduce (m,l) across tx ----------------
    #pragma unroll
    for (int i = 0; i < 4; ++i) {
        redm[(ty*4 + i)*17 + tx] = mloc[i];
        redl[(ty*4 + i)*17 + tx] = lloc[i];
    }
    __syncthreads();
    if (tid < 64) {
        float m = -1e30f;
        for (int x = 0; x < 16; ++x) m = fmaxf(m, redm[tid*17 + x]);
        float l = 0.f;
        for (int x = 0; x < 16; ++x) l += redl[tid*17 + x] * __expf(redm[tid*17 + x] - m);
        mrow[tid] = m;
        linv[tid] = 1.0f / l;
    }
    __syncthreads();

    // ---------------- phase 2 ----------------
    float ctx[4][8] = {};
    const int cx = tx * 8;
    for (int t0 = 0; t0 < SEQ; t0 += 64) {
        __syncthreads();
        // V tile (stride 132 -> aligned float4)
        for (int i = tid; i < 64*32; i += 256) {
            int r = i >> 5, c = (i & 31) << 2;
            float4 v = *(const float4*)(Vg + (size_t)(t0 + r)*Dh + c);
            *(float4*)&Ts[r*132 + c] = v;
        }
        // finalize softmax weights for this tile
        #pragma unroll
        for (int i = 0; i < 4; ++i) {
            int r = ty*4 + i;
            int rg = s0 + r;
            float m = mrow[r], li = linv[r];
            #pragma unroll
            for (int j = 0; j < 4; ++j) {
                int t = t0 + tx + 16*j;
                float sc = wb[(size_t)rg*SEQ + t];
                float w = __expf(sc - m) * li;
                wb[(size_t)rg*SEQ + t] = w;
                wS[r*65 + tx + 16*j] = w;
            }
        }
        __syncthreads();
        // ctx += w @ V
        #pragma unroll 2
        for (int tt = 0; tt < 64; ++tt) {
            float4 v0 = *(const float4*)&Ts[tt*132 + cx];
            float4 v1 = *(const float4*)&Ts[tt*132 + cx + 4];
            #pragma unroll
            for (int i = 0; i < 4; ++i) {
                float w = wS[(ty*4 + i)*65 + tt];
                ctx[i][0] += w*v0.x; ctx[i][1] += w*v0.y;
                ctx[i][2] += w*v0.z; ctx[i][3] += w*v0.w;
                ctx[i][4] += w*v1.x; ctx[i][5] += w*v1.y;
                ctx[i][6] += w*v1.z; ctx[i][7] += w*v1.w;
            }
        }
    }

    float* Cb = g_CTX + bh*SEQ*Dh;
    #pragma unroll
    for (int i = 0; i < 4; ++i) {
        #pragma unroll
        for (int j = 0; j < 8; j += 4) {
            float4 v = make_float4(ctx[i][j], ctx[i][j+1], ctx[i][j+2], ctx[i][j+3]);
            *(float4*)(Cb + (size_t)(s0 + ty*4 + i)*Dh + cx + j) = v;
        }
    }
}

// ---------------------------------------------------------------------------
// Output projection: out[b,s,n] = sum_{h,d} ctx[b,h,s,d] * Wd[n, h*Dh+d] + bd[n]
// ---------------------------------------------------------------------------
__global__ __launch_bounds__(256) void out_gemm_kernel(
    const float* __restrict__ Wd, const float* __restrict__ bd,
    float* __restrict__ out)
{
    extern __shared__ float sm[];
    float* Xs = sm;             // 64 x 129
    float* Ws = sm + 64*129;    // 64 x 129

    const int m0 = blockIdx.y * 64;
    const int n0 = blockIdx.x * 64;     // 0 or 64
    const int tid = threadIdx.x;
    const int tx = tid & 15, ty = tid >> 4;
    const int b = m0 >> 11;
    const int sbase = m0 & 2047;

    float acc[4][4] = {};
    for (int kt = 0; kt < NHEAD; ++kt) {
        __syncthreads();
        for (int i = tid; i < 64*32; i += 256) {
            int r = i >> 5, c = (i & 31) << 2;
            float4 v = *(const float4*)(g_CTX +
                (((size_t)(b*NHEAD + kt))*SEQ + sbase + r)*Dh + c);
            Xs[r*129 + c]   = v.x; Xs[r*129 + c+1] = v.y;
            Xs[r*129 + c+2] = v.z; Xs[r*129 + c+3] = v.w;
            float4 w = *(const float4*)(Wd + (size_t)(n0 + r)*NHD + kt*Dh + c);
            Ws[r*129 + c]   = w.x; Ws[r*129 + c+1] = w.y;
            Ws[r*129 + c+2] = w.z; Ws[r*129 + c+3] = w.w;
        }
        __syncthreads();
        #pragma unroll 4
        for (int k = 0; k < Dh; ++k) {
            float a[4];
            #pragma unroll
            for (int i = 0; i < 4; ++i) a[i] = Xs[(ty*4 + i)*129 + k];
            #pragma unroll
            for (int j = 0; j < 4; ++j) {
                float bv = Ws[(tx + 16*j)*129 + k];
                #pragma unroll
                for (int i = 0; i < 4; ++i) acc[i][j] += a[i] * bv;
            }
        }
    }

    #pragma unroll
    for (int i = 0; i < 4; ++i) {
        int m = m0 + ty*4 + i;
        #pragma unroll
        for (int j = 0; j < 4; ++j) {
            int n = n0 + tx + 16*j;
            out[(size_t)m*Dh + n] = acc[i][j] + bd[n];
        }
    }
}

// ---------------------------------------------------------------------------
extern "C" void kernel_launch(void* const* d_in, const int* in_sizes, int n_in,
                              void* d_out, int out_size)
{
    (void)in_sizes; (void)n_in; (void)out_size;
    const float* x    = (const float*)d_in[0];
    const int*   mask = (const int*)  d_in[1];
    const float* Wq   = (const float*)d_in[2];
    const float* bq   = (const float*)d_in[3];
    const float* Wk   = (const float*)d_in[4];
    const float* bk   = (const float*)d_in[5];
    const float* Wv   = (const float*)d_in[6];
    const float* bv   = (const float*)d_in[7];
    const float* Wd   = (const float*)d_in[8];
    const float* bd   = (const float*)d_in[9];

    float* out     = (float*)d_out;                         // (B,S,D)
    float* weights = out + (size_t)NB*SEQ*Dh;               // (B,H,S,S)

    const size_t smem_gemm = (size_t)2*64*129*sizeof(float);     // 66048 B
    const size_t smem_attn = (size_t)(64*129 + 64*132 + 64*65 +
                                      64*17*2 + 128) * sizeof(float);  // 92672 B

    cudaFuncSetAttribute(qkv_gemm_kernel,
        cudaFuncAttributeMaxDynamicSharedMemorySize, (int)smem_gemm);
    cudaFuncSetAttribute(attn_kernel,
        cudaFuncAttributeMaxDynamicSharedMemorySize, (int)smem_attn);
    cudaFuncSetAttribute(out_gemm_kernel,
        cudaFuncAttributeMaxDynamicSharedMemorySize, (int)smem_gemm);

    dim3 blk(256);
    dim3 g1(NHD/64, MROWS/64);          // (32, 64)
    qkv_gemm_kernel<<<g1, blk, smem_gemm>>>(x, Wq, bq, 0);
    qkv_gemm_kernel<<<g1, blk, smem_gemm>>>(x, Wk, bk, 1);
    qkv_gemm_kernel<<<g1, blk, smem_gemm>>>(x, Wv, bv, 2);

    dim3 g2(SEQ/64, NHEAD, NB);         // (32, 16, 2)
    attn_kernel<<<g2, blk, smem_attn>>>(mask, weights);

    dim3 g3(Dh/64, MROWS/64);           // (2, 64)
    out_gemm_kernel<<<g3, blk, smem_gemm>>>(Wd, bd, out);
}